// round 7
// baseline (speedup 1.0000x reference)
#include <cuda_runtime.h>
#include <math.h>

#define N_NODES  50000
#define N_EDGES  800000
#define N_GRAPHS 1000
#define F_INPUT  128
#define HID      64
#define OUT_F    16
#define BN_EPS   1e-5f
#define NBLK256  ((N_NODES + 255) / 256)   // 196

// ---------------- scratch (static device globals; no allocation) ------------
__device__ float g_B0[N_NODES * HID];      // v (post MLP, pre-BN)
__device__ float g_B1[N_NODES * HID];      // t (transformed features)
__device__ float g_stats[3 * 2 * HID];     // per-layer sum, sumsq
__device__ float g_pooled[N_GRAPHS * HID]; // segment max
// CSR scratch
__device__ int g_deg[N_NODES];
__device__ int g_off[N_NODES + 1];
__device__ int g_cur[N_NODES];
__device__ int g_csr[N_EDGES];
__device__ int g_bsum[NBLK256];

// ---------------- helpers ---------------------------------------------------
__device__ __forceinline__ void atomicMaxF(float* addr, float val) {
    if (val >= 0.f) atomicMax((int*)addr, __float_as_int(val));
    else            atomicMin((unsigned int*)addr, __float_as_uint(val));
}
__device__ __forceinline__ void add4(float4& a, const float4 b) {
    a.x += b.x; a.y += b.y; a.z += b.z; a.w += b.w;
}

// ---------------- init ------------------------------------------------------
__global__ void init_kernel() {
    int i = blockIdx.x * blockDim.x + threadIdx.x;
    if (i < N_GRAPHS * HID) g_pooled[i] = -INFINITY;
    if (i < N_NODES) g_deg[i] = 0;
    if (i < 3 * 2 * HID) g_stats[i] = 0.f;
}

// ---------------- CSR build -------------------------------------------------
__global__ void hist_kernel(const int* __restrict__ ei) {
    int e = blockIdx.x * blockDim.x + threadIdx.x;
    if (e < N_EDGES) atomicAdd(&g_deg[__ldg(&ei[N_EDGES + e])], 1);
}
__global__ void scanA_kernel() {   // per-block degree sums
    __shared__ int sh[256];
    int tid = threadIdx.x;
    int n = blockIdx.x * 256 + tid;
    sh[tid] = (n < N_NODES) ? g_deg[n] : 0;
    __syncthreads();
    for (int s = 128; s > 0; s >>= 1) {
        if (tid < s) sh[tid] += sh[tid + s];
        __syncthreads();
    }
    if (tid == 0) g_bsum[blockIdx.x] = sh[0];
}
__global__ void scanC_kernel() {   // block offset + per-node offsets
    __shared__ int sh[256];
    __shared__ int boff_sh;
    int tid = threadIdx.x;
    // reduce bsum[0 .. blockIdx)
    int part = 0;
    for (int j = tid; j < blockIdx.x; j += 256) part += g_bsum[j];
    sh[tid] = part;
    __syncthreads();
    for (int s = 128; s > 0; s >>= 1) {
        if (tid < s) sh[tid] += sh[tid + s];
        __syncthreads();
    }
    if (tid == 0) boff_sh = sh[0];
    __syncthreads();
    int boff = boff_sh;
    int n = blockIdx.x * 256 + tid;
    int v = (n < N_NODES) ? g_deg[n] : 0;
    sh[tid] = v;
    __syncthreads();
    for (int d = 1; d < 256; d <<= 1) {
        int t = (tid >= d) ? sh[tid - d] : 0;
        __syncthreads();
        sh[tid] += t;
        __syncthreads();
    }
    if (n < N_NODES) {
        int off = boff + sh[tid] - v;
        g_off[n] = off;
        g_cur[n] = off;
    }
    if (blockIdx.x == NBLK256 - 1 && tid == 255)
        g_off[N_NODES] = boff + sh[255];
}
__global__ void fill_kernel(const int* __restrict__ ei) {
    int e = blockIdx.x * blockDim.x + threadIdx.x;
    if (e >= N_EDGES) return;
    int s = __ldg(&ei[e]);
    int d = __ldg(&ei[N_EDGES + e]);
    int pos = atomicAdd(&g_cur[d], 1);
    g_csr[pos] = s;
}

// ---------------- gemm1: t = (BN-affine(h)) @ W (+folded bias) -> B1 --------
// 128-row tile, 256 threads, 4x8 register blocking.
template <int IN_F, bool FOLDED>
__global__ void __launch_bounds__(256) gemm1_kernel(
    const float* __restrict__ h_in, const float* __restrict__ w,
    const float* __restrict__ gamma, const float* __restrict__ beta,
    int stats_layer)
{
    extern __shared__ float smem[];
    float* w_sh = smem;                 // [IN_F][HID]
    float* h_sh = smem + IN_F * HID;    // [128][IN_F]
    __shared__ float sc[HID], sf[HID], bias_sh[HID];
    int tid = threadIdx.x;

    if (FOLDED) {
        if (tid < HID) {
            const float* stats = g_stats + stats_layer * 2 * HID;
            float inv_n = 1.f / (float)N_NODES;
            float mu  = stats[tid] * inv_n;
            float var = stats[HID + tid] * inv_n - mu * mu;
            float s = gamma[tid] * rsqrtf(var + BN_EPS);
            sc[tid] = s;
            sf[tid] = beta[tid] - mu * s;
        }
        __syncthreads();
    }

    const float* h = FOLDED ? g_B0 : h_in;
    for (int i = tid; i < IN_F * HID / 4; i += 256) {
        float4 v = ((const float4*)w)[i];
        if (FOLDED) {
            float s = sc[(i * 4) >> 6];   // k index (row of W)
            v.x *= s; v.y *= s; v.z *= s; v.w *= s;
        }
        ((float4*)w_sh)[i] = v;
    }

    int rowbase = blockIdx.x * 128;
    int nrows = N_NODES - rowbase; if (nrows > 128) nrows = 128;
    const float4* hbase = (const float4*)(h + (long)rowbase * IN_F);
    for (int i = tid; i < 128 * IN_F / 4; i += 256) {
        int r = i / (IN_F / 4);
        ((float4*)h_sh)[i] = (r < nrows) ? hbase[i] : make_float4(0.f, 0.f, 0.f, 0.f);
    }

    if (FOLDED && tid < HID) {
        float b = 0.f;
#pragma unroll 8
        for (int k = 0; k < HID; k++)
            b += sf[k] * __ldg(&w[k * HID + tid]);
        bias_sh[tid] = b;
    }
    __syncthreads();

    int rg = tid >> 3, cg = tid & 7;          // 32 row groups x 8 col groups
    int r0 = rg * 4, c0 = cg * 8;
    float acc[4][8];
#pragma unroll
    for (int r = 0; r < 4; r++)
#pragma unroll
        for (int j = 0; j < 8; j++) acc[r][j] = 0.f;

    for (int k = 0; k < IN_F; k += 4) {
        float4 av[4];
#pragma unroll
        for (int r = 0; r < 4; r++)
            av[r] = *(const float4*)&h_sh[(r0 + r) * IN_F + k];
#pragma unroll
        for (int kk = 0; kk < 4; kk++) {
            float4 w0 = *(const float4*)&w_sh[(k + kk) * HID + c0];
            float4 w1 = *(const float4*)&w_sh[(k + kk) * HID + c0 + 4];
#pragma unroll
            for (int r = 0; r < 4; r++) {
                float a = (kk == 0) ? av[r].x : (kk == 1) ? av[r].y
                         : (kk == 2) ? av[r].z : av[r].w;
                acc[r][0] += a * w0.x; acc[r][1] += a * w0.y;
                acc[r][2] += a * w0.z; acc[r][3] += a * w0.w;
                acc[r][4] += a * w1.x; acc[r][5] += a * w1.y;
                acc[r][6] += a * w1.z; acc[r][7] += a * w1.w;
            }
        }
    }

    float4 b0 = make_float4(0.f, 0.f, 0.f, 0.f), b1v = b0;
    if (FOLDED) {
        b0  = *(const float4*)&bias_sh[c0];
        b1v = *(const float4*)&bias_sh[c0 + 4];
    }
#pragma unroll
    for (int r = 0; r < 4; r++) {
        if (r0 + r < nrows) {
            long off = (long)(rowbase + r0 + r) * HID + c0;
            *(float4*)&g_B1[off] = make_float4(acc[r][0] + b0.x, acc[r][1] + b0.y,
                                               acc[r][2] + b0.z, acc[r][3] + b0.w);
            *(float4*)&g_B1[off + 4] = make_float4(acc[r][4] + b1v.x, acc[r][5] + b1v.y,
                                                   acc[r][6] + b1v.z, acc[r][7] + b1v.w);
        }
    }
}

// ---------------- fused agg + gemm2 (256 threads) ---------------------------
__global__ void __launch_bounds__(256) agg_gemm2_kernel(
    const float* __restrict__ b1, const float* __restrict__ w2,
    const float* __restrict__ b2, int layer)
{
    extern __shared__ float smem[];
    float* w_sh = smem;                 // [HID][HID]
    float* u_sh = smem + HID * HID;     // [128][HID]
    __shared__ float s_sum[HID];
    __shared__ float s_sq[HID];
    int tid = threadIdx.x;

    for (int i = tid; i < HID * HID / 4; i += 256)
        ((float4*)w_sh)[i] = ((const float4*)w2)[i];
    if (tid < HID) { s_sum[tid] = 0.f; s_sq[tid] = 0.f; }

    int rowbase = blockIdx.x * 128;
    int nrows = N_NODES - rowbase; if (nrows > 128) nrows = 128;

    // phase 1: gather; 1024 tasks (128 rows x 8 slices), 4 per thread
#pragma unroll
    for (int it = 0; it < 4; it++) {
        int task = it * 256 + tid;
        int row = task >> 3;
        int c = (task & 7) * 8;
        float4 a0 = make_float4(0.f, 0.f, 0.f, 0.f), a1 = a0;
        if (row < nrows) {
            int node = rowbase + row;
            long base = (long)node * HID + c;
            a0 = *(const float4*)&g_B1[base];
            a1 = *(const float4*)&g_B1[base + 4];
            int p = g_off[node], end = g_off[node + 1];
            for (; p + 4 <= end; p += 4) {
                int s0 = __ldg(&g_csr[p]);
                int s1 = __ldg(&g_csr[p + 1]);
                int s2 = __ldg(&g_csr[p + 2]);
                int s3 = __ldg(&g_csr[p + 3]);
                const float4* t0 = (const float4*)(g_B1 + (long)s0 * HID + c);
                const float4* t1 = (const float4*)(g_B1 + (long)s1 * HID + c);
                const float4* t2 = (const float4*)(g_B1 + (long)s2 * HID + c);
                const float4* t3 = (const float4*)(g_B1 + (long)s3 * HID + c);
                float4 v00 = __ldg(t0), v01 = __ldg(t0 + 1);
                float4 v10 = __ldg(t1), v11 = __ldg(t1 + 1);
                float4 v20 = __ldg(t2), v21 = __ldg(t2 + 1);
                float4 v30 = __ldg(t3), v31 = __ldg(t3 + 1);
                add4(a0, v00); add4(a1, v01);
                add4(a0, v10); add4(a1, v11);
                add4(a0, v20); add4(a1, v21);
                add4(a0, v30); add4(a1, v31);
            }
            for (; p < end; p++) {
                int s0 = __ldg(&g_csr[p]);
                const float4* t0 = (const float4*)(g_B1 + (long)s0 * HID + c);
                add4(a0, __ldg(t0)); add4(a1, __ldg(t0 + 1));
            }
            float4 bb0 = *(const float4*)&b1[c];
            float4 bb1 = *(const float4*)&b1[c + 4];
            a0.x = fmaxf(a0.x + bb0.x, 0.f); a0.y = fmaxf(a0.y + bb0.y, 0.f);
            a0.z = fmaxf(a0.z + bb0.z, 0.f); a0.w = fmaxf(a0.w + bb0.w, 0.f);
            a1.x = fmaxf(a1.x + bb1.x, 0.f); a1.y = fmaxf(a1.y + bb1.y, 0.f);
            a1.z = fmaxf(a1.z + bb1.z, 0.f); a1.w = fmaxf(a1.w + bb1.w, 0.f);
        }
        *(float4*)&u_sh[row * HID + c]     = a0;
        *(float4*)&u_sh[row * HID + c + 4] = a1;
    }
    __syncthreads();

    // phase 2: GEMM (4x8 per thread)
    int rg = tid >> 3, cg = tid & 7;
    int r0 = rg * 4, c0 = cg * 8;
    float acc[4][8];
#pragma unroll
    for (int r = 0; r < 4; r++)
#pragma unroll
        for (int j = 0; j < 8; j++) acc[r][j] = 0.f;

    for (int k = 0; k < HID; k += 4) {
        float4 av[4];
#pragma unroll
        for (int r = 0; r < 4; r++)
            av[r] = *(const float4*)&u_sh[(r0 + r) * HID + k];
#pragma unroll
        for (int kk = 0; kk < 4; kk++) {
            float4 w0 = *(const float4*)&w_sh[(k + kk) * HID + c0];
            float4 w1 = *(const float4*)&w_sh[(k + kk) * HID + c0 + 4];
#pragma unroll
            for (int r = 0; r < 4; r++) {
                float a = (kk == 0) ? av[r].x : (kk == 1) ? av[r].y
                         : (kk == 2) ? av[r].z : av[r].w;
                acc[r][0] += a * w0.x; acc[r][1] += a * w0.y;
                acc[r][2] += a * w0.z; acc[r][3] += a * w0.w;
                acc[r][4] += a * w1.x; acc[r][5] += a * w1.y;
                acc[r][6] += a * w1.z; acc[r][7] += a * w1.w;
            }
        }
    }

    float4 bb0 = *(const float4*)&b2[c0];
    float4 bb1 = *(const float4*)&b2[c0 + 4];
    float ls[8] = {0,0,0,0,0,0,0,0};
    float lq[8] = {0,0,0,0,0,0,0,0};
#pragma unroll
    for (int r = 0; r < 4; r++) {
        if (r0 + r < nrows) {
            float o[8];
            o[0] = fmaxf(acc[r][0] + bb0.x, 0.f); o[1] = fmaxf(acc[r][1] + bb0.y, 0.f);
            o[2] = fmaxf(acc[r][2] + bb0.z, 0.f); o[3] = fmaxf(acc[r][3] + bb0.w, 0.f);
            o[4] = fmaxf(acc[r][4] + bb1.x, 0.f); o[5] = fmaxf(acc[r][5] + bb1.y, 0.f);
            o[6] = fmaxf(acc[r][6] + bb1.z, 0.f); o[7] = fmaxf(acc[r][7] + bb1.w, 0.f);
            long off = (long)(rowbase + r0 + r) * HID + c0;
            *(float4*)&g_B0[off]     = make_float4(o[0], o[1], o[2], o[3]);
            *(float4*)&g_B0[off + 4] = make_float4(o[4], o[5], o[6], o[7]);
#pragma unroll
            for (int j = 0; j < 8; j++) { ls[j] += o[j]; lq[j] += o[j] * o[j]; }
        }
    }
#pragma unroll
    for (int j = 0; j < 8; j++) {
        atomicAdd(&s_sum[c0 + j], ls[j]);
        atomicAdd(&s_sq[c0 + j],  lq[j]);
    }
    __syncthreads();
    float* stats = g_stats + layer * 2 * HID;
    if (tid < HID) {
        atomicAdd(&stats[tid], s_sum[tid]);
        atomicAdd(&stats[HID + tid], s_sq[tid]);
    }
}

// ---------------- pool: run-length segment max (batch is sorted) ------------
__global__ void __launch_bounds__(256) pool_kernel(
    const int* __restrict__ batch,
    const float* __restrict__ gamma, const float* __restrict__ beta)
{
    __shared__ float sc[HID], sf[HID];
    int tid = threadIdx.x;
    if (tid < HID) {
        const float* stats = g_stats + 2 * 2 * HID;   // layer 2
        float inv_n = 1.f / (float)N_NODES;
        float mu  = stats[tid] * inv_n;
        float var = stats[HID + tid] * inv_n - mu * mu;
        float s = gamma[tid] * rsqrtf(var + BN_EPS);
        sc[tid] = s;
        sf[tid] = beta[tid] - mu * s;
    }
    __syncthreads();

    int base = blockIdx.x * 128;
    int r = tid >> 6;       // 0..3
    int c = tid & 63;
    float cur = -INFINITY;
    int curg = -1;
    int lim = base + 128; if (lim > N_NODES) lim = N_NODES;
    for (int n = base + r; n < lim; n += 4) {
        int g = __ldg(&batch[n]);
        float v = g_B0[(long)n * HID + c] * sc[c] + sf[c];
        if (g != curg) {
            if (curg >= 0) atomicMaxF(&g_pooled[curg * HID + c], cur);
            curg = g; cur = v;
        } else {
            cur = fmaxf(cur, v);
        }
    }
    if (curg >= 0) atomicMaxF(&g_pooled[curg * HID + c], cur);
}

// ---------------- head: relu(pooled@lin1+b1)@lin2+b2 ------------------------
__global__ void __launch_bounds__(128) head_kernel(
    const float* __restrict__ lin1_w, const float* __restrict__ lin1_b,
    const float* __restrict__ lin2_w, const float* __restrict__ lin2_b,
    float* __restrict__ out)
{
    __shared__ float w1_sh[HID * HID];
    __shared__ float w2_sh[HID * OUT_F];
    __shared__ float p_sh[4][HID];
    __shared__ float h_sh[4][HID];
    int tid = threadIdx.x, warp = tid >> 5, lane = tid & 31;

    for (int i = tid; i < HID * HID / 4; i += 128)
        ((float4*)w1_sh)[i] = ((const float4*)lin1_w)[i];
    for (int i = tid; i < HID * OUT_F / 4; i += 128)
        ((float4*)w2_sh)[i] = ((const float4*)lin2_w)[i];

    int g = blockIdx.x * 4 + warp;
    float p0 = g_pooled[g * HID + lane];
    float p1 = g_pooled[g * HID + lane + 32];
    if (!isfinite(p0)) p0 = 0.f;
    if (!isfinite(p1)) p1 = 0.f;
    p_sh[warp][lane] = p0;
    p_sh[warp][lane + 32] = p1;
    __syncthreads();

    float acc0 = lin1_b[lane], acc1 = lin1_b[lane + 32];
#pragma unroll 8
    for (int k = 0; k < HID; k++) {
        float pv = p_sh[warp][k];
        acc0 += pv * w1_sh[k * HID + lane];
        acc1 += pv * w1_sh[k * HID + lane + 32];
    }
    h_sh[warp][lane]      = fmaxf(acc0, 0.f);
    h_sh[warp][lane + 32] = fmaxf(acc1, 0.f);
    __syncwarp();

    if (lane < OUT_F) {
        float acc = lin2_b[lane];
#pragma unroll 8
        for (int k = 0; k < HID; k++)
            acc += h_sh[warp][k] * w2_sh[k * OUT_F + lane];
        out[g * OUT_F + lane] = acc;
    }
}

// ---------------- launch ----------------------------------------------------
extern "C" void kernel_launch(void* const* d_in, const int* in_sizes, int n_in,
                              void* d_out, int out_size)
{
    const float* x     = (const float*)d_in[0];
    const int*   ei    = (const int*)d_in[1];    // int32 (JAX x64 disabled)
    const int*   batch = (const int*)d_in[2];
    const float* l0_w1 = (const float*)d_in[3];
    const float* l0_b1 = (const float*)d_in[4];
    const float* l0_w2 = (const float*)d_in[5];
    const float* l0_b2 = (const float*)d_in[6];
    const float* l0_g  = (const float*)d_in[7];
    const float* l0_be = (const float*)d_in[8];
    const float* ws1   = (const float*)d_in[9];
    const float* bs1   = (const float*)d_in[10];
    const float* ws2   = (const float*)d_in[11];
    const float* bs2   = (const float*)d_in[12];
    const float* gms   = (const float*)d_in[13];
    const float* bts   = (const float*)d_in[14];
    const float* lin1w = (const float*)d_in[15];
    const float* lin1b = (const float*)d_in[16];
    const float* lin2w = (const float*)d_in[17];
    const float* lin2b = (const float*)d_in[18];
    float* out = (float*)d_out;

    const int GEMM_BLOCKS = (N_NODES + 127) / 128;     // 391
    const int EDGE_BLOCKS = (N_EDGES + 255) / 256;     // 3125

    const int SMEM_G1_L0 = (F_INPUT * HID + 128 * F_INPUT) * 4;  // 96 KB
    const int SMEM_G1_LN = (HID * HID + 128 * HID) * 4;          // 48 KB
    const int SMEM_AG2   = (HID * HID + 128 * HID) * 4;          // 48 KB
    cudaFuncSetAttribute(gemm1_kernel<F_INPUT, false>,
                         cudaFuncAttributeMaxDynamicSharedMemorySize, SMEM_G1_L0);
    cudaFuncSetAttribute(gemm1_kernel<HID, true>,
                         cudaFuncAttributeMaxDynamicSharedMemorySize, SMEM_G1_LN);
    cudaFuncSetAttribute(agg_gemm2_kernel,
                         cudaFuncAttributeMaxDynamicSharedMemorySize, SMEM_AG2);

    // ---- init + CSR build (reused by all 3 layers) ----
    init_kernel<<<(N_GRAPHS * HID + 255) / 256, 256>>>();
    hist_kernel<<<EDGE_BLOCKS, 256>>>(ei);
    scanA_kernel<<<NBLK256, 256>>>();
    scanC_kernel<<<NBLK256, 256>>>();
    fill_kernel<<<EDGE_BLOCKS, 256>>>(ei);

    // ---- layer 0 (128 -> 64) ----
    gemm1_kernel<F_INPUT, false><<<GEMM_BLOCKS, 256, SMEM_G1_L0>>>(
        x, l0_w1, nullptr, nullptr, 0);
    agg_gemm2_kernel<<<GEMM_BLOCKS, 256, SMEM_AG2>>>(l0_b1, l0_w2, l0_b2, 0);

    // ---- layer 1 (64 -> 64), folds layer-0 BN into weights inline ----
    gemm1_kernel<HID, true><<<GEMM_BLOCKS, 256, SMEM_G1_LN>>>(
        nullptr, ws1, l0_g, l0_be, 0);
    agg_gemm2_kernel<<<GEMM_BLOCKS, 256, SMEM_AG2>>>(bs1, ws2, bs2, 1);

    // ---- layer 2 (64 -> 64), folds layer-1 BN inline ----
    gemm1_kernel<HID, true><<<GEMM_BLOCKS, 256, SMEM_G1_LN>>>(
        nullptr, ws1 + HID * HID, gms, bts, 1);
    agg_gemm2_kernel<<<GEMM_BLOCKS, 256, SMEM_AG2>>>(
        bs1 + HID, ws2 + HID * HID, bs2 + HID, 2);

    // ---- pool (computes layer-2 BN inline) + head ----
    pool_kernel<<<GEMM_BLOCKS, 256>>>(batch, gms + HID, bts + HID);
    head_kernel<<<N_GRAPHS / 4, 128>>>(lin1w, lin1b, lin2w, lin2b, out);
}

// round 8
// speedup vs baseline: 1.1008x; 1.1008x over previous
#include <cuda_runtime.h>
#include <cuda_fp16.h>
#include <math.h>

#define N_NODES  50000
#define N_EDGES  800000
#define N_GRAPHS 1000
#define F_INPUT  128
#define HID      64
#define OUT_F    16
#define BN_EPS   1e-5f
#define NBLK256  ((N_NODES + 255) / 256)   // 196

// ---------------- scratch (static device globals; no allocation) ------------
__device__ float  g_B0[N_NODES * HID];      // v (post MLP, pre-BN), fp32
__device__ __half g_B1h[N_NODES * HID];     // t (transformed features), fp16
__device__ float  g_stats[3 * 2 * HID];     // per-layer sum, sumsq
__device__ float  g_pooled[N_GRAPHS * HID]; // segment max
// CSR scratch
__device__ int g_deg[N_NODES];
__device__ int g_off[N_NODES + 1];
__device__ int g_cur[N_NODES];
__device__ int g_csr[N_EDGES];
__device__ int g_bsum[NBLK256];

// ---------------- helpers ---------------------------------------------------
__device__ __forceinline__ void atomicMaxF(float* addr, float val) {
    if (val >= 0.f) atomicMax((int*)addr, __float_as_int(val));
    else            atomicMin((unsigned int*)addr, __float_as_uint(val));
}
// accumulate 8 halfs (one uint4) into two float4 accumulators
__device__ __forceinline__ void accH8(float4& A, float4& B, uint4 q) {
    float2 f;
    f = __half22float2(*(__half2*)&q.x); A.x += f.x; A.y += f.y;
    f = __half22float2(*(__half2*)&q.y); A.z += f.x; A.w += f.y;
    f = __half22float2(*(__half2*)&q.z); B.x += f.x; B.y += f.y;
    f = __half22float2(*(__half2*)&q.w); B.z += f.x; B.w += f.y;
}

// ---------------- init ------------------------------------------------------
__global__ void init_kernel() {
    int i = blockIdx.x * blockDim.x + threadIdx.x;
    if (i < N_GRAPHS * HID) g_pooled[i] = -INFINITY;
    if (i < N_NODES) g_deg[i] = 0;
    if (i < 3 * 2 * HID) g_stats[i] = 0.f;
}

// ---------------- CSR build -------------------------------------------------
__global__ void hist_kernel(const int* __restrict__ ei) {
    int e = blockIdx.x * blockDim.x + threadIdx.x;
    if (e < N_EDGES) atomicAdd(&g_deg[__ldg(&ei[N_EDGES + e])], 1);
}
__global__ void scanA_kernel() {   // per-block degree sums
    __shared__ int sh[256];
    int tid = threadIdx.x;
    int n = blockIdx.x * 256 + tid;
    sh[tid] = (n < N_NODES) ? g_deg[n] : 0;
    __syncthreads();
    for (int s = 128; s > 0; s >>= 1) {
        if (tid < s) sh[tid] += sh[tid + s];
        __syncthreads();
    }
    if (tid == 0) g_bsum[blockIdx.x] = sh[0];
}
__global__ void scanC_kernel() {   // block offset + per-node offsets
    __shared__ int sh[256];
    __shared__ int boff_sh;
    int tid = threadIdx.x;
    int part = 0;
    for (int j = tid; j < blockIdx.x; j += 256) part += g_bsum[j];
    sh[tid] = part;
    __syncthreads();
    for (int s = 128; s > 0; s >>= 1) {
        if (tid < s) sh[tid] += sh[tid + s];
        __syncthreads();
    }
    if (tid == 0) boff_sh = sh[0];
    __syncthreads();
    int boff = boff_sh;
    int n = blockIdx.x * 256 + tid;
    int v = (n < N_NODES) ? g_deg[n] : 0;
    sh[tid] = v;
    __syncthreads();
    for (int d = 1; d < 256; d <<= 1) {
        int t = (tid >= d) ? sh[tid - d] : 0;
        __syncthreads();
        sh[tid] += t;
        __syncthreads();
    }
    if (n < N_NODES) {
        int off = boff + sh[tid] - v;
        g_off[n] = off;
        g_cur[n] = off;
    }
    if (blockIdx.x == NBLK256 - 1 && tid == 255)
        g_off[N_NODES] = boff + sh[255];
}
__global__ void fill_kernel(const int* __restrict__ ei) {
    int e = blockIdx.x * blockDim.x + threadIdx.x;
    if (e >= N_EDGES) return;
    int s = __ldg(&ei[e]);
    int d = __ldg(&ei[N_EDGES + e]);
    int pos = atomicAdd(&g_cur[d], 1);
    g_csr[pos] = s;
}

// ---------------- gemm1: t = (BN-affine(h)) @ W (+folded bias) -> B1h (fp16)
// 128-row tile, 256 threads, 4x8 register blocking.
template <int IN_F, bool FOLDED>
__global__ void __launch_bounds__(256) gemm1_kernel(
    const float* __restrict__ h_in, const float* __restrict__ w,
    const float* __restrict__ gamma, const float* __restrict__ beta,
    int stats_layer)
{
    extern __shared__ float smem[];
    float* w_sh = smem;                 // [IN_F][HID]
    float* h_sh = smem + IN_F * HID;    // [128][IN_F]
    __shared__ float sc[HID], sf[HID], bias_sh[HID];
    int tid = threadIdx.x;

    if (FOLDED) {
        if (tid < HID) {
            const float* stats = g_stats + stats_layer * 2 * HID;
            float inv_n = 1.f / (float)N_NODES;
            float mu  = stats[tid] * inv_n;
            float var = stats[HID + tid] * inv_n - mu * mu;
            float s = gamma[tid] * rsqrtf(var + BN_EPS);
            sc[tid] = s;
            sf[tid] = beta[tid] - mu * s;
        }
        __syncthreads();
    }

    const float* h = FOLDED ? g_B0 : h_in;
    for (int i = tid; i < IN_F * HID / 4; i += 256) {
        float4 v = ((const float4*)w)[i];
        if (FOLDED) {
            float s = sc[(i * 4) >> 6];   // k index (row of W)
            v.x *= s; v.y *= s; v.z *= s; v.w *= s;
        }
        ((float4*)w_sh)[i] = v;
    }

    int rowbase = blockIdx.x * 128;
    int nrows = N_NODES - rowbase; if (nrows > 128) nrows = 128;
    const float4* hbase = (const float4*)(h + (long)rowbase * IN_F);
    for (int i = tid; i < 128 * IN_F / 4; i += 256) {
        int r = i / (IN_F / 4);
        ((float4*)h_sh)[i] = (r < nrows) ? hbase[i] : make_float4(0.f, 0.f, 0.f, 0.f);
    }

    if (FOLDED && tid < HID) {
        float b = 0.f;
#pragma unroll 8
        for (int k = 0; k < HID; k++)
            b += sf[k] * __ldg(&w[k * HID + tid]);
        bias_sh[tid] = b;
    }
    __syncthreads();

    int rg = tid >> 3, cg = tid & 7;          // 32 row groups x 8 col groups
    int r0 = rg * 4, c0 = cg * 8;
    float acc[4][8];
#pragma unroll
    for (int r = 0; r < 4; r++)
#pragma unroll
        for (int j = 0; j < 8; j++) acc[r][j] = 0.f;

    for (int k = 0; k < IN_F; k += 4) {
        float4 av[4];
#pragma unroll
        for (int r = 0; r < 4; r++)
            av[r] = *(const float4*)&h_sh[(r0 + r) * IN_F + k];
#pragma unroll
        for (int kk = 0; kk < 4; kk++) {
            float4 w0 = *(const float4*)&w_sh[(k + kk) * HID + c0];
            float4 w1 = *(const float4*)&w_sh[(k + kk) * HID + c0 + 4];
#pragma unroll
            for (int r = 0; r < 4; r++) {
                float a = (kk == 0) ? av[r].x : (kk == 1) ? av[r].y
                         : (kk == 2) ? av[r].z : av[r].w;
                acc[r][0] += a * w0.x; acc[r][1] += a * w0.y;
                acc[r][2] += a * w0.z; acc[r][3] += a * w0.w;
                acc[r][4] += a * w1.x; acc[r][5] += a * w1.y;
                acc[r][6] += a * w1.z; acc[r][7] += a * w1.w;
            }
        }
    }

    float4 b0 = make_float4(0.f, 0.f, 0.f, 0.f), b1v = b0;
    if (FOLDED) {
        b0  = *(const float4*)&bias_sh[c0];
        b1v = *(const float4*)&bias_sh[c0 + 4];
    }
#pragma unroll
    for (int r = 0; r < 4; r++) {
        if (r0 + r < nrows) {
            uint4 pack;
            __half2* ph = (__half2*)&pack;
            ph[0] = __floats2half2_rn(acc[r][0] + b0.x,  acc[r][1] + b0.y);
            ph[1] = __floats2half2_rn(acc[r][2] + b0.z,  acc[r][3] + b0.w);
            ph[2] = __floats2half2_rn(acc[r][4] + b1v.x, acc[r][5] + b1v.y);
            ph[3] = __floats2half2_rn(acc[r][6] + b1v.z, acc[r][7] + b1v.w);
            *(uint4*)&g_B1h[(long)(rowbase + r0 + r) * HID + c0] = pack;
        }
    }
}

// ---------------- fused agg + gemm2 (256 threads, fp16 gather) --------------
// Phase 1: u[row] = relu(B1h[row] + sum B1h[csr] + b1) in fp32 smem.
// Phase 2: v = relu(u @ w2 + b2) -> B0 (fp32); accumulate BN stats.
__global__ void __launch_bounds__(256) agg_gemm2_kernel(
    const float* __restrict__ b1, const float* __restrict__ w2,
    const float* __restrict__ b2, int layer)
{
    extern __shared__ float smem[];
    float* w_sh = smem;                 // [HID][HID]
    float* u_sh = smem + HID * HID;     // [128][HID]
    __shared__ float s_sum[HID];
    __shared__ float s_sq[HID];
    int tid = threadIdx.x;

    for (int i = tid; i < HID * HID / 4; i += 256)
        ((float4*)w_sh)[i] = ((const float4*)w2)[i];
    if (tid < HID) { s_sum[tid] = 0.f; s_sq[tid] = 0.f; }

    int rowbase = blockIdx.x * 128;
    int nrows = N_NODES - rowbase; if (nrows > 128) nrows = 128;

    // phase 1: gather; 512 tasks (128 rows x 4 slices of 16 feats), 2/thread
#pragma unroll
    for (int it = 0; it < 2; it++) {
        int task = it * 256 + tid;
        int row = task >> 2;
        int c = (task & 3) * 16;          // feature offset (16 halfs = 32B)
        float4 A0 = make_float4(0.f,0.f,0.f,0.f), A1 = A0, A2 = A0, A3 = A0;
        if (row < nrows) {
            int node = rowbase + row;
            const uint4* self = (const uint4*)&g_B1h[(long)node * HID + c];
            accH8(A0, A1, __ldg(self));
            accH8(A2, A3, __ldg(self + 1));
            int p = g_off[node], end = g_off[node + 1];
            for (; p + 4 <= end; p += 4) {
                int s0 = __ldg(&g_csr[p]);
                int s1 = __ldg(&g_csr[p + 1]);
                int s2 = __ldg(&g_csr[p + 2]);
                int s3 = __ldg(&g_csr[p + 3]);
                const uint4* t0 = (const uint4*)&g_B1h[(long)s0 * HID + c];
                const uint4* t1 = (const uint4*)&g_B1h[(long)s1 * HID + c];
                const uint4* t2 = (const uint4*)&g_B1h[(long)s2 * HID + c];
                const uint4* t3 = (const uint4*)&g_B1h[(long)s3 * HID + c];
                uint4 q00 = __ldg(t0), q01 = __ldg(t0 + 1);
                uint4 q10 = __ldg(t1), q11 = __ldg(t1 + 1);
                uint4 q20 = __ldg(t2), q21 = __ldg(t2 + 1);
                uint4 q30 = __ldg(t3), q31 = __ldg(t3 + 1);
                accH8(A0, A1, q00); accH8(A2, A3, q01);
                accH8(A0, A1, q10); accH8(A2, A3, q11);
                accH8(A0, A1, q20); accH8(A2, A3, q21);
                accH8(A0, A1, q30); accH8(A2, A3, q31);
            }
            for (; p < end; p++) {
                int s0 = __ldg(&g_csr[p]);
                const uint4* t0 = (const uint4*)&g_B1h[(long)s0 * HID + c];
                accH8(A0, A1, __ldg(t0));
                accH8(A2, A3, __ldg(t0 + 1));
            }
            float4 bb0 = *(const float4*)&b1[c];
            float4 bb1 = *(const float4*)&b1[c + 4];
            float4 bb2 = *(const float4*)&b1[c + 8];
            float4 bb3 = *(const float4*)&b1[c + 12];
            A0.x = fmaxf(A0.x + bb0.x, 0.f); A0.y = fmaxf(A0.y + bb0.y, 0.f);
            A0.z = fmaxf(A0.z + bb0.z, 0.f); A0.w = fmaxf(A0.w + bb0.w, 0.f);
            A1.x = fmaxf(A1.x + bb1.x, 0.f); A1.y = fmaxf(A1.y + bb1.y, 0.f);
            A1.z = fmaxf(A1.z + bb1.z, 0.f); A1.w = fmaxf(A1.w + bb1.w, 0.f);
            A2.x = fmaxf(A2.x + bb2.x, 0.f); A2.y = fmaxf(A2.y + bb2.y, 0.f);
            A2.z = fmaxf(A2.z + bb2.z, 0.f); A2.w = fmaxf(A2.w + bb2.w, 0.f);
            A3.x = fmaxf(A3.x + bb3.x, 0.f); A3.y = fmaxf(A3.y + bb3.y, 0.f);
            A3.z = fmaxf(A3.z + bb3.z, 0.f); A3.w = fmaxf(A3.w + bb3.w, 0.f);
        }
        *(float4*)&u_sh[row * HID + c]      = A0;
        *(float4*)&u_sh[row * HID + c + 4]  = A1;
        *(float4*)&u_sh[row * HID + c + 8]  = A2;
        *(float4*)&u_sh[row * HID + c + 12] = A3;
    }
    __syncthreads();

    // phase 2: GEMM (4x8 per thread)
    int rg = tid >> 3, cg = tid & 7;
    int r0 = rg * 4, c0 = cg * 8;
    float acc[4][8];
#pragma unroll
    for (int r = 0; r < 4; r++)
#pragma unroll
        for (int j = 0; j < 8; j++) acc[r][j] = 0.f;

    for (int k = 0; k < HID; k += 4) {
        float4 av[4];
#pragma unroll
        for (int r = 0; r < 4; r++)
            av[r] = *(const float4*)&u_sh[(r0 + r) * HID + k];
#pragma unroll
        for (int kk = 0; kk < 4; kk++) {
            float4 w0 = *(const float4*)&w_sh[(k + kk) * HID + c0];
            float4 w1 = *(const float4*)&w_sh[(k + kk) * HID + c0 + 4];
#pragma unroll
            for (int r = 0; r < 4; r++) {
                float a = (kk == 0) ? av[r].x : (kk == 1) ? av[r].y
                         : (kk == 2) ? av[r].z : av[r].w;
                acc[r][0] += a * w0.x; acc[r][1] += a * w0.y;
                acc[r][2] += a * w0.z; acc[r][3] += a * w0.w;
                acc[r][4] += a * w1.x; acc[r][5] += a * w1.y;
                acc[r][6] += a * w1.z; acc[r][7] += a * w1.w;
            }
        }
    }

    float4 bb0 = *(const float4*)&b2[c0];
    float4 bb1 = *(const float4*)&b2[c0 + 4];
    float ls[8] = {0,0,0,0,0,0,0,0};
    float lq[8] = {0,0,0,0,0,0,0,0};
#pragma unroll
    for (int r = 0; r < 4; r++) {
        if (r0 + r < nrows) {
            float o[8];
            o[0] = fmaxf(acc[r][0] + bb0.x, 0.f); o[1] = fmaxf(acc[r][1] + bb0.y, 0.f);
            o[2] = fmaxf(acc[r][2] + bb0.z, 0.f); o[3] = fmaxf(acc[r][3] + bb0.w, 0.f);
            o[4] = fmaxf(acc[r][4] + bb1.x, 0.f); o[5] = fmaxf(acc[r][5] + bb1.y, 0.f);
            o[6] = fmaxf(acc[r][6] + bb1.z, 0.f); o[7] = fmaxf(acc[r][7] + bb1.w, 0.f);
            long off = (long)(rowbase + r0 + r) * HID + c0;
            *(float4*)&g_B0[off]     = make_float4(o[0], o[1], o[2], o[3]);
            *(float4*)&g_B0[off + 4] = make_float4(o[4], o[5], o[6], o[7]);
#pragma unroll
            for (int j = 0; j < 8; j++) { ls[j] += o[j]; lq[j] += o[j] * o[j]; }
        }
    }
#pragma unroll
    for (int j = 0; j < 8; j++) {
        atomicAdd(&s_sum[c0 + j], ls[j]);
        atomicAdd(&s_sq[c0 + j],  lq[j]);
    }
    __syncthreads();
    float* stats = g_stats + layer * 2 * HID;
    if (tid < HID) {
        atomicAdd(&stats[tid], s_sum[tid]);
        atomicAdd(&stats[HID + tid], s_sq[tid]);
    }
}

// ---------------- pool: run-length segment max (batch is sorted) ------------
__global__ void __launch_bounds__(256) pool_kernel(
    const int* __restrict__ batch,
    const float* __restrict__ gamma, const float* __restrict__ beta)
{
    __shared__ float sc[HID], sf[HID];
    int tid = threadIdx.x;
    if (tid < HID) {
        const float* stats = g_stats + 2 * 2 * HID;   // layer 2
        float inv_n = 1.f / (float)N_NODES;
        float mu  = stats[tid] * inv_n;
        float var = stats[HID + tid] * inv_n - mu * mu;
        float s = gamma[tid] * rsqrtf(var + BN_EPS);
        sc[tid] = s;
        sf[tid] = beta[tid] - mu * s;
    }
    __syncthreads();

    int base = blockIdx.x * 128;
    int r = tid >> 6;       // 0..3
    int c = tid & 63;
    float cur = -INFINITY;
    int curg = -1;
    int lim = base + 128; if (lim > N_NODES) lim = N_NODES;
    for (int n = base + r; n < lim; n += 4) {
        int g = __ldg(&batch[n]);
        float v = g_B0[(long)n * HID + c] * sc[c] + sf[c];
        if (g != curg) {
            if (curg >= 0) atomicMaxF(&g_pooled[curg * HID + c], cur);
            curg = g; cur = v;
        } else {
            cur = fmaxf(cur, v);
        }
    }
    if (curg >= 0) atomicMaxF(&g_pooled[curg * HID + c], cur);
}

// ---------------- head: relu(pooled@lin1+b1)@lin2+b2 ------------------------
__global__ void __launch_bounds__(128) head_kernel(
    const float* __restrict__ lin1_w, const float* __restrict__ lin1_b,
    const float* __restrict__ lin2_w, const float* __restrict__ lin2_b,
    float* __restrict__ out)
{
    __shared__ float w1_sh[HID * HID];
    __shared__ float w2_sh[HID * OUT_F];
    __shared__ float p_sh[4][HID];
    __shared__ float h_sh[4][HID];
    int tid = threadIdx.x, warp = tid >> 5, lane = tid & 31;

    for (int i = tid; i < HID * HID / 4; i += 128)
        ((float4*)w1_sh)[i] = ((const float4*)lin1_w)[i];
    for (int i = tid; i < HID * OUT_F / 4; i += 128)
        ((float4*)w2_sh)[i] = ((const float4*)lin2_w)[i];

    int g = blockIdx.x * 4 + warp;
    float p0 = g_pooled[g * HID + lane];
    float p1 = g_pooled[g * HID + lane + 32];
    if (!isfinite(p0)) p0 = 0.f;
    if (!isfinite(p1)) p1 = 0.f;
    p_sh[warp][lane] = p0;
    p_sh[warp][lane + 32] = p1;
    __syncthreads();

    float acc0 = lin1_b[lane], acc1 = lin1_b[lane + 32];
#pragma unroll 8
    for (int k = 0; k < HID; k++) {
        float pv = p_sh[warp][k];
        acc0 += pv * w1_sh[k * HID + lane];
        acc1 += pv * w1_sh[k * HID + lane + 32];
    }
    h_sh[warp][lane]      = fmaxf(acc0, 0.f);
    h_sh[warp][lane + 32] = fmaxf(acc1, 0.f);
    __syncwarp();

    if (lane < OUT_F) {
        float acc = lin2_b[lane];
#pragma unroll 8
        for (int k = 0; k < HID; k++)
            acc += h_sh[warp][k] * w2_sh[k * OUT_F + lane];
        out[g * OUT_F + lane] = acc;
    }
}

// ---------------- launch ----------------------------------------------------
extern "C" void kernel_launch(void* const* d_in, const int* in_sizes, int n_in,
                              void* d_out, int out_size)
{
    const float* x     = (const float*)d_in[0];
    const int*   ei    = (const int*)d_in[1];    // int32 (JAX x64 disabled)
    const int*   batch = (const int*)d_in[2];
    const float* l0_w1 = (const float*)d_in[3];
    const float* l0_b1 = (const float*)d_in[4];
    const float* l0_w2 = (const float*)d_in[5];
    const float* l0_b2 = (const float*)d_in[6];
    const float* l0_g  = (const float*)d_in[7];
    const float* l0_be = (const float*)d_in[8];
    const float* ws1   = (const float*)d_in[9];
    const float* bs1   = (const float*)d_in[10];
    const float* ws2   = (const float*)d_in[11];
    const float* bs2   = (const float*)d_in[12];
    const float* gms   = (const float*)d_in[13];
    const float* bts   = (const float*)d_in[14];
    const float* lin1w = (const float*)d_in[15];
    const float* lin1b = (const float*)d_in[16];
    const float* lin2w = (const float*)d_in[17];
    const float* lin2b = (const float*)d_in[18];
    float* out = (float*)d_out;

    const int GEMM_BLOCKS = (N_NODES + 127) / 128;     // 391
    const int EDGE_BLOCKS = (N_EDGES + 255) / 256;     // 3125

    const int SMEM_G1_L0 = (F_INPUT * HID + 128 * F_INPUT) * 4;  // 96 KB
    const int SMEM_G1_LN = (HID * HID + 128 * HID) * 4;          // 48 KB
    const int SMEM_AG2   = (HID * HID + 128 * HID) * 4;          // 48 KB
    cudaFuncSetAttribute(gemm1_kernel<F_INPUT, false>,
                         cudaFuncAttributeMaxDynamicSharedMemorySize, SMEM_G1_L0);
    cudaFuncSetAttribute(gemm1_kernel<HID, true>,
                         cudaFuncAttributeMaxDynamicSharedMemorySize, SMEM_G1_LN);
    cudaFuncSetAttribute(agg_gemm2_kernel,
                         cudaFuncAttributeMaxDynamicSharedMemorySize, SMEM_AG2);

    // ---- init + CSR build (reused by all 3 layers) ----
    init_kernel<<<(N_GRAPHS * HID + 255) / 256, 256>>>();
    hist_kernel<<<EDGE_BLOCKS, 256>>>(ei);
    scanA_kernel<<<NBLK256, 256>>>();
    scanC_kernel<<<NBLK256, 256>>>();
    fill_kernel<<<EDGE_BLOCKS, 256>>>(ei);

    // ---- layer 0 (128 -> 64) ----
    gemm1_kernel<F_INPUT, false><<<GEMM_BLOCKS, 256, SMEM_G1_L0>>>(
        x, l0_w1, nullptr, nullptr, 0);
    agg_gemm2_kernel<<<GEMM_BLOCKS, 256, SMEM_AG2>>>(l0_b1, l0_w2, l0_b2, 0);

    // ---- layer 1 (64 -> 64), folds layer-0 BN into weights inline ----
    gemm1_kernel<HID, true><<<GEMM_BLOCKS, 256, SMEM_G1_LN>>>(
        nullptr, ws1, l0_g, l0_be, 0);
    agg_gemm2_kernel<<<GEMM_BLOCKS, 256, SMEM_AG2>>>(bs1, ws2, bs2, 1);

    // ---- layer 2 (64 -> 64), folds layer-1 BN inline ----
    gemm1_kernel<HID, true><<<GEMM_BLOCKS, 256, SMEM_G1_LN>>>(
        nullptr, ws1 + HID * HID, gms, bts, 1);
    agg_gemm2_kernel<<<GEMM_BLOCKS, 256, SMEM_AG2>>>(
        bs1 + HID, ws2 + HID * HID, bs2 + HID, 2);

    // ---- pool (computes layer-2 BN inline) + head ----
    pool_kernel<<<GEMM_BLOCKS, 256>>>(batch, gms + HID, bts + HID);
    head_kernel<<<N_GRAPHS / 4, 128>>>(lin1w, lin1b, lin2w, lin2b, out);
}